// round 13
// baseline (speedup 1.0000x reference)
#include <cuda_runtime.h>
#include <math.h>

#define BT 32
#define NP 2048
#define NC 7
#define KK 16
#define EPS 1e-5f

// Scratch (allocation-free rule: __device__ globals)
__device__ int   g_idx[BT * NP * KK];     // 4 MB
__device__ float g_u[BT * NP * 64];       // 16 MB  (BN1-folded x@(W1a-W1b)^T + t1)
__device__ float g_v[BT * NP * 64];       // 16 MB  (BN1-folded x@W1b^T)

__device__ __forceinline__ float gelu_exact(float x) {
    return 0.5f * x * (1.0f + erff(x * 0.7071067811865475f));
}

// ------------------------------------------------------------------
// Kernel 1: exact KNN (top-16 smallest d2, tie-break = smallest index)
// Pass A: distances only (FMNMX sorted insert). Pass B: index collect.
// ------------------------------------------------------------------
__global__ __launch_bounds__(128) void knn_kernel(const float* __restrict__ x) {
    __shared__ float4 pts[NP];          // x,y,z,|xyz|^2  (32 KB)
    __shared__ int    tiebuf[128 * 8];  // exact-tie overflow

    const int b   = blockIdx.y;
    const int tid = threadIdx.x;
    const int p   = blockIdx.x * 128 + tid;

    for (int i = tid; i < NP; i += 128) {
        const float* row = x + ((size_t)b * NP + i) * NC;
        float X = row[0], Y = row[1], Z = row[2];
        pts[i] = make_float4(X, Y, Z, fmaf(Z, Z, fmaf(Y, Y, X * X)));
    }
    __syncthreads();

    const float4 me = pts[p];
    const float xp = me.x, yp = me.y, zp = me.z, sqp = me.w;

    float bd[KK];
    #pragma unroll
    for (int j = 0; j < KK; ++j) bd[j] = 3.402823466e+38f;
    float b15 = 3.402823466e+38f;

    // Pass A: maintain 16 smallest distances (sorted asc via min/max bubble)
    for (int q = 0; q < NP; ++q) {
        float4 o = pts[q];
        float dot = fmaf(zp, o.z, fmaf(yp, o.y, xp * o.x));
        float d2  = fmaf(-2.0f, dot, sqp + o.w);
        if (d2 < b15) {
            float c = d2;
            #pragma unroll
            for (int j = 0; j < KK; ++j) {
                float t = bd[j];
                bd[j] = fminf(t, c);
                c     = fmaxf(t, c);
            }
            b15 = bd[KK - 1];
        }
    }

    // Pass B: recompute identically, collect indices. All d2 < tau belong to
    // the set; ties at tau filled smallest-index-first (matches lax.top_k).
    const float tau = b15;
    int cnt = 0, nt = 0;
    int* outp = g_idx + ((size_t)b * NP + p) * KK;
    for (int q = 0; q < NP; ++q) {
        float4 o = pts[q];
        float dot = fmaf(zp, o.z, fmaf(yp, o.y, xp * o.x));
        float d2  = fmaf(-2.0f, dot, sqp + o.w);
        if (d2 < tau) {
            outp[cnt++] = q;          // count of strict-less is <= 15 by defn
        } else if (d2 == tau) {
            if (nt < 8) tiebuf[tid * 8 + nt] = q;
            nt++;
        }
    }
    for (int t = 0; t < nt && cnt < KK; ++t)
        outp[cnt++] = tiebuf[tid * 8 + t];
}

// ------------------------------------------------------------------
// Kernel 2: per-point u' = (x@(W1a-W1b)^T)*s1 + t1,  v' = (x@W1b^T)*s1
// (BN1 folded; layer-1 GEMM becomes per-point instead of per-edge)
// ------------------------------------------------------------------
__global__ void uv_kernel(const float* __restrict__ x, const float* __restrict__ W1,
                          const float* __restrict__ g1, const float* __restrict__ b1,
                          const float* __restrict__ m1, const float* __restrict__ v1) {
    int id = blockIdx.x * blockDim.x + threadIdx.x;   // id = p*64 + o
    if (id >= BT * NP * 64) return;
    int o = id & 63;
    int p = id >> 6;

    float s1 = g1[o] * rsqrtf(v1[o] + EPS);
    float t1 = fmaf(-m1[o], s1, b1[o]);

    const float* xr = x + (size_t)p * NC;
    const float* w  = W1 + o * (2 * NC);
    float du = 0.f, dv = 0.f;
    #pragma unroll
    for (int c = 0; c < NC; ++c) {
        float xc = xr[c];
        float wb = w[NC + c];
        dv = fmaf(xc, wb, dv);
        du = fmaf(xc, w[c] - wb, du);
    }
    g_u[id] = fmaf(du, s1, t1);
    g_v[id] = dv * s1;
}

// ------------------------------------------------------------------
// Kernel 3: h1 = gelu(u'[p] + v'[j]);  h2 = h1 @ W2'^T (+t2);
// out = max(gelu(max_k h2), gelu(min_k h2))   [gelu is valley-unimodal]
// Inner product via fma.rn.f32x2 (2x fp32 FMA throughput on sm_103a).
// Thread t owns output channel o=t; BN2-folded W2 row lives in 32 b64 regs.
// ------------------------------------------------------------------
__global__ __launch_bounds__(128, 4) void mlp_kernel(
    const float* __restrict__ W2,
    const float* __restrict__ g2, const float* __restrict__ b2,
    const float* __restrict__ m2, const float* __restrict__ v2,
    float* __restrict__ out) {

    __shared__ __align__(16) float h1s[KK * 64];   // 4 KB
    __shared__ float us[64];
    __shared__ int   idxs[KK];

    const int tid = threadIdx.x;       // = output channel o

    float s2 = g2[tid] * rsqrtf(v2[tid] + EPS);
    float t2 = fmaf(-m2[tid], s2, b2[tid]);

    // Pack BN2-scaled W2 row into 32 x b64 registers (pairs of f32)
    unsigned long long w2r[32];
    const float* wrow = W2 + tid * 64;
    #pragma unroll
    for (int i = 0; i < 32; ++i) {
        float a  = wrow[2 * i]     * s2;
        float bb = wrow[2 * i + 1] * s2;
        asm("mov.b64 %0, {%1,%2};" : "=l"(w2r[i]) : "f"(a), "f"(bb));
    }
    const ulonglong2* h1u = reinterpret_cast<const ulonglong2*>(h1s);

    const int g0 = blockIdx.x * 16;    // 16 points per block
    for (int pt = 0; pt < 16; ++pt) {
        const int g = g0 + pt;         // global point id = b*2048 + p
        __syncthreads();               // protect smem reuse across points
        if (tid < KK) idxs[tid] = g_idx[g * KK + tid];
        if (tid < 64) us[tid]   = g_u[g * 64 + tid];
        __syncthreads();

        const int bbase = (g >> 11) << 11;   // b * 2048
        #pragma unroll
        for (int j = 0; j < 8; ++j) {        // build h1 (1024 vals, gelu'd)
            int vloc = tid + 128 * j;
            int k = vloc >> 6, c = vloc & 63;
            int nb = idxs[k];
            float val = us[c] + g_v[(size_t)(bbase + nb) * 64 + c];
            h1s[vloc] = gelu_exact(val);
        }
        __syncthreads();

        float vmx = -3.402823466e+38f, vmn = 3.402823466e+38f;
        for (int k = 0; k < KK; ++k) {
            unsigned long long a0 = 0ULL, a1 = 0ULL, a2 = 0ULL, a3 = 0ULL;
            const ulonglong2* hk = h1u + k * 16;   // 64 floats = 16 x ull2
            #pragma unroll
            for (int i = 0; i < 16; ++i) {
                ulonglong2 hv = hk[i];             // broadcast LDS.128
                if (i & 1) {
                    asm("fma.rn.f32x2 %0, %1, %2, %0;" : "+l"(a1) : "l"(hv.x), "l"(w2r[2 * i]));
                    asm("fma.rn.f32x2 %0, %1, %2, %0;" : "+l"(a3) : "l"(hv.y), "l"(w2r[2 * i + 1]));
                } else {
                    asm("fma.rn.f32x2 %0, %1, %2, %0;" : "+l"(a0) : "l"(hv.x), "l"(w2r[2 * i]));
                    asm("fma.rn.f32x2 %0, %1, %2, %0;" : "+l"(a2) : "l"(hv.y), "l"(w2r[2 * i + 1]));
                }
            }
            float f0, f1, f2, f3, f4, f5, f6, f7;
            asm("mov.b64 {%0,%1}, %2;" : "=f"(f0), "=f"(f1) : "l"(a0));
            asm("mov.b64 {%0,%1}, %2;" : "=f"(f2), "=f"(f3) : "l"(a1));
            asm("mov.b64 {%0,%1}, %2;" : "=f"(f4), "=f"(f5) : "l"(a2));
            asm("mov.b64 {%0,%1}, %2;" : "=f"(f6), "=f"(f7) : "l"(a3));
            float h2 = ((f0 + f1) + (f2 + f3)) + ((f4 + f5) + (f6 + f7)) + t2;
            vmx = fmaxf(vmx, h2);
            vmn = fminf(vmn, h2);
        }
        out[(size_t)g * 128 + tid] = fmaxf(gelu_exact(vmx), gelu_exact(vmn));
    }
}

// ------------------------------------------------------------------
extern "C" void kernel_launch(void* const* d_in, const int* in_sizes, int n_in,
                              void* d_out, int out_size) {
    const float* x   = (const float*)d_in[0];
    const float* W1  = (const float*)d_in[1];
    const float* g1  = (const float*)d_in[2];
    const float* b1  = (const float*)d_in[3];
    const float* m1  = (const float*)d_in[4];
    const float* v1  = (const float*)d_in[5];
    const float* W2  = (const float*)d_in[6];
    const float* g2  = (const float*)d_in[7];
    const float* b2  = (const float*)d_in[8];
    const float* m2  = (const float*)d_in[9];
    const float* v2  = (const float*)d_in[10];
    float* out = (float*)d_out;

    knn_kernel<<<dim3(NP / 128, BT), 128>>>(x);
    uv_kernel<<<(BT * NP * 64) / 256, 256>>>(x, W1, g1, b1, m1, v1);
    mlp_kernel<<<(BT * NP) / 16, 128>>>(W2, g2, b2, m2, v2, out);
}

// round 16
// speedup vs baseline: 1.1000x; 1.1000x over previous
#include <cuda_runtime.h>
#include <math.h>

#define BT 32
#define NP 2048
#define NC 7
#define KK 16
#define EPS 1e-5f

// Scratch (allocation-free rule: __device__ globals)
__device__ int   g_idx[BT * NP * KK];     // 4 MB
__device__ float g_u[BT * NP * 64];       // 16 MB  (BN1-folded x@(W1a-W1b)^T + t1)
__device__ float g_v[BT * NP * 64];       // 16 MB  (BN1-folded x@W1b^T)

__device__ __forceinline__ float gelu_exact(float x) {
    return 0.5f * x * (1.0f + erff(x * 0.7071067811865475f));
}

// ------------------------------------------------------------------
// Kernel 1: exact KNN, split-scan: 2 threads per query, each scans 1024
// candidates. Merge via bitonic half-cleaner: tau = max_i min(a_i, b_{15-i}).
// Pass B is set-based (downstream max-pool is order-invariant):
//   half0 strict-less  -> slots [0, cntA)            (forward)
//   half1 strict-less  -> slots [16-cntB, 16)        (backward)
//   ties at tau        -> gap slots [cntA, 16-cntB), smallest index first
// ------------------------------------------------------------------
__global__ __launch_bounds__(256) void knn_kernel(const float* __restrict__ x) {
    __shared__ float4 pts[NP];          // 32 KB
    __shared__ int    tiebuf[256 * 8];  // 8 KB, exact-tie overflow

    const int b    = blockIdx.y;
    const int tid  = threadIdx.x;
    const int ql   = tid >> 1;          // query within block (0..127)
    const int half = tid & 1;           // which half of candidates
    const int p    = blockIdx.x * 128 + ql;

    for (int i = tid; i < NP; i += 256) {
        const float* row = x + ((size_t)b * NP + i) * NC;
        float X = row[0], Y = row[1], Z = row[2];
        pts[i] = make_float4(X, Y, Z, fmaf(Z, Z, fmaf(Y, Y, X * X)));
    }
    __syncthreads();

    const float4 me = pts[p];
    const float xp = me.x, yp = me.y, zp = me.z, sqp = me.w;
    const int q0 = half << 10;          // 0 or 1024

    float bd[KK];
    #pragma unroll
    for (int j = 0; j < KK; ++j) bd[j] = 3.402823466e+38f;
    float b15 = 3.402823466e+38f;

    // Pass A: 16 smallest distances over this thread's half (sorted asc)
    for (int q = q0; q < q0 + 1024; ++q) {
        float4 o = pts[q];
        float dot = fmaf(zp, o.z, fmaf(yp, o.y, xp * o.x));
        float d2  = fmaf(-2.0f, dot, sqp + o.w);
        if (d2 < b15) {
            float c = d2;
            #pragma unroll
            for (int j = 0; j < KK; ++j) {
                float t = bd[j];
                bd[j] = fminf(t, c);
                c     = fmaxf(t, c);
            }
            b15 = bd[KK - 1];
        }
    }

    // Merge across the thread pair: tau = 16th smallest of the union.
    // Half-cleaner: {min(a_i, b_{15-i})} is the multiset of the 16 smallest;
    // tau = max of it. Symmetric in (a,b), so both lanes get the same tau.
    float tau = -3.402823466e+38f;
    #pragma unroll
    for (int i = 0; i < KK; ++i) {
        float pb = __shfl_xor_sync(0xffffffffu, bd[KK - 1 - i], 1);
        tau = fmaxf(tau, fminf(bd[i], pb));
    }

    // Pass B: collect indices over this half. Strict-less total <= 15, so
    // forward (half0) and backward (half1) strict regions never collide.
    int cnt = 0, nt = 0;
    int* outp = g_idx + ((size_t)b * NP + p) * KK;
    for (int q = q0; q < q0 + 1024; ++q) {
        float4 o = pts[q];
        float dot = fmaf(zp, o.z, fmaf(yp, o.y, xp * o.x));
        float d2  = fmaf(-2.0f, dot, sqp + o.w);
        if (d2 < tau) {
            outp[half ? (KK - 1 - cnt) : cnt] = q;
            cnt++;
        } else if (d2 == tau) {
            if (nt < 8) tiebuf[tid * 8 + nt] = q;
            nt++;
        }
    }
    int cntO = __shfl_xor_sync(0xffffffffu, cnt, 1);
    int ntO  = __shfl_xor_sync(0xffffffffu, nt, 1);
    int cntA = half ? cntO : cnt;      // half0 strict count
    int cntB = half ? cnt  : cntO;     // half1 strict count
    int ntA  = half ? ntO  : nt;       // half0 tie count
    int rem  = KK - cntA - cntB;       // size of tie gap [cntA, 16-cntB)
    int myn  = min(nt, 8);
    int start, take;
    if (half == 0) {                   // half0 ties first (smaller indices)
        start = cntA;
        take  = min(myn, rem);
    } else {
        int aT = min(min(ntA, 8), rem);   // exactly what half0 wrote
        start = cntA + aT;
        take  = min(myn, rem - aT);
    }
    for (int t = 0; t < take; ++t)
        outp[start + t] = tiebuf[tid * 8 + t];
}

// ------------------------------------------------------------------
// Kernel 2: per-point u' = (x@(W1a-W1b)^T)*s1 + t1,  v' = (x@W1b^T)*s1
// ------------------------------------------------------------------
__global__ void uv_kernel(const float* __restrict__ x, const float* __restrict__ W1,
                          const float* __restrict__ g1, const float* __restrict__ b1,
                          const float* __restrict__ m1, const float* __restrict__ v1) {
    int id = blockIdx.x * blockDim.x + threadIdx.x;   // id = p*64 + o
    if (id >= BT * NP * 64) return;
    int o = id & 63;
    int p = id >> 6;

    float s1 = g1[o] * rsqrtf(v1[o] + EPS);
    float t1 = fmaf(-m1[o], s1, b1[o]);

    const float* xr = x + (size_t)p * NC;
    const float* w  = W1 + o * (2 * NC);
    float du = 0.f, dv = 0.f;
    #pragma unroll
    for (int c = 0; c < NC; ++c) {
        float xc = xr[c];
        float wb = w[NC + c];
        dv = fmaf(xc, wb, dv);
        du = fmaf(xc, w[c] - wb, du);
    }
    g_u[id] = fmaf(du, s1, t1);
    g_v[id] = dv * s1;
}

// ------------------------------------------------------------------
// Kernel 3 (pipelined): h1 = gelu(u'[p] + v'[j]); h2 = h1 @ W2'^T (+t2);
// out = max(gelu(max_k h2), gelu(min_k h2))  [gelu is valley-unimodal].
// Double-buffered h1 in smem; next point's idx/u/v LDGs are issued BEFORE
// the current GEMM so their latency hides under ~1500 FFMA cycles.
// One __syncthreads() per point. Inner product via fma.rn.f32x2.
// Thread t: output channel o=t for GEMM; builds h1 chunk k=t>>3, c=(t&7)*8.
// ------------------------------------------------------------------
__global__ __launch_bounds__(128, 4) void mlp_kernel(
    const float* __restrict__ W2,
    const float* __restrict__ g2, const float* __restrict__ b2,
    const float* __restrict__ m2, const float* __restrict__ v2,
    float* __restrict__ out) {

    __shared__ __align__(16) float h1s[2][KK * 64];   // 2 x 4 KB

    const int tid = threadIdx.x;

    float s2 = g2[tid] * rsqrtf(v2[tid] + EPS);
    float t2 = fmaf(-m2[tid], s2, b2[tid]);

    // Pack BN2-scaled W2 row into 32 x b64 registers (pairs of f32)
    unsigned long long w2r[32];
    const float* wrow = W2 + tid * 64;
    #pragma unroll
    for (int i = 0; i < 32; ++i) {
        float a  = wrow[2 * i]     * s2;
        float bb = wrow[2 * i + 1] * s2;
        asm("mov.b64 %0, {%1,%2};" : "=l"(w2r[i]) : "f"(a), "f"(bb));
    }

    const int g0    = blockIdx.x * 16;       // 16 points per block (same batch)
    const int kq    = tid >> 3;              // k index this thread builds
    const int c0    = (tid & 7) * 8;         // channel base this thread builds
    const int bbase = (g0 >> 11) << 11;      // batch * 2048
    const int lastg = BT * NP - 1;

    // Prologue: build h1 for point g0 into buffer 0
    {
        int nb = g_idx[(size_t)g0 * KK + kq];
        const float* vp = g_v + ((size_t)(bbase + nb) * 64 + c0);
        float4 va = *(const float4*)vp, vb = *(const float4*)(vp + 4);
        const float* up = g_u + ((size_t)g0 * 64 + c0);
        float4 ua = *(const float4*)up, ub = *(const float4*)(up + 4);
        float4 ra, rb;
        ra.x = gelu_exact(ua.x + va.x); ra.y = gelu_exact(ua.y + va.y);
        ra.z = gelu_exact(ua.z + va.z); ra.w = gelu_exact(ua.w + va.w);
        rb.x = gelu_exact(ub.x + vb.x); rb.y = gelu_exact(ub.y + vb.y);
        rb.z = gelu_exact(ub.z + vb.z); rb.w = gelu_exact(ub.w + vb.w);
        float* hp = &h1s[0][kq * 64 + c0];
        *(float4*)hp = ra; *(float4*)(hp + 4) = rb;
    }
    int nb1 = g_idx[(size_t)min(g0 + 1, lastg) * KK + kq];
    __syncthreads();

    for (int pt = 0; pt < 16; ++pt) {
        const int buf = pt & 1;
        const int g   = g0 + pt;

        // Prefetch for point pt+1 (clamped indices: memory-safe, unused at pt=15)
        const int gp = min(g + 1, lastg);
        const float* vp = g_v + ((size_t)(bbase + nb1) * 64 + c0);
        float4 va = *(const float4*)vp, vb = *(const float4*)(vp + 4);
        const float* up = g_u + ((size_t)gp * 64 + c0);
        float4 ua = *(const float4*)up, ub = *(const float4*)(up + 4);
        int nb2 = g_idx[(size_t)min(g + 2, lastg) * KK + kq];

        // GEMM over h1s[buf] (broadcast LDS.128 + fma.rn.f32x2)
        const ulonglong2* h1u = reinterpret_cast<const ulonglong2*>(h1s[buf]);
        float vmx = -3.402823466e+38f, vmn = 3.402823466e+38f;
        #pragma unroll 4
        for (int k = 0; k < KK; ++k) {
            unsigned long long a0 = 0ULL, a1 = 0ULL, a2 = 0ULL, a3 = 0ULL;
            const ulonglong2* hk = h1u + k * 16;   // 64 floats = 16 x ull2
            #pragma unroll
            for (int i = 0; i < 16; ++i) {
                ulonglong2 hv = hk[i];
                if (i & 1) {
                    asm("fma.rn.f32x2 %0, %1, %2, %0;" : "+l"(a1) : "l"(hv.x), "l"(w2r[2 * i]));
                    asm("fma.rn.f32x2 %0, %1, %2, %0;" : "+l"(a3) : "l"(hv.y), "l"(w2r[2 * i + 1]));
                } else {
                    asm("fma.rn.f32x2 %0, %1, %2, %0;" : "+l"(a0) : "l"(hv.x), "l"(w2r[2 * i]));
                    asm("fma.rn.f32x2 %0, %1, %2, %0;" : "+l"(a2) : "l"(hv.y), "l"(w2r[2 * i + 1]));
                }
            }
            asm("add.rn.f32x2 %0, %0, %1;" : "+l"(a0) : "l"(a1));
            asm("add.rn.f32x2 %0, %0, %1;" : "+l"(a2) : "l"(a3));
            asm("add.rn.f32x2 %0, %0, %1;" : "+l"(a0) : "l"(a2));
            float f0, f1;
            asm("mov.b64 {%0,%1}, %2;" : "=f"(f0), "=f"(f1) : "l"(a0));
            float h2 = f0 + f1 + t2;
            vmx = fmaxf(vmx, h2);
            vmn = fminf(vmn, h2);
        }
        out[(size_t)g * 128 + tid] = fmaxf(gelu_exact(vmx), gelu_exact(vmn));

        // Build h1 for pt+1 into the other buffer (loads already in flight)
        {
            float4 ra, rb;
            ra.x = gelu_exact(ua.x + va.x); ra.y = gelu_exact(ua.y + va.y);
            ra.z = gelu_exact(ua.z + va.z); ra.w = gelu_exact(ua.w + va.w);
            rb.x = gelu_exact(ub.x + vb.x); rb.y = gelu_exact(ub.y + vb.y);
            rb.z = gelu_exact(ub.z + vb.z); rb.w = gelu_exact(ub.w + vb.w);
            float* hp = &h1s[buf ^ 1][kq * 64 + c0];
            *(float4*)hp = ra; *(float4*)(hp + 4) = rb;
        }
        nb1 = nb2;
        __syncthreads();   // writes to buf^1 visible before next GEMM reads it
    }
}

// ------------------------------------------------------------------
extern "C" void kernel_launch(void* const* d_in, const int* in_sizes, int n_in,
                              void* d_out, int out_size) {
    const float* x   = (const float*)d_in[0];
    const float* W1  = (const float*)d_in[1];
    const float* g1  = (const float*)d_in[2];
    const float* b1  = (const float*)d_in[3];
    const float* m1  = (const float*)d_in[4];
    const float* v1  = (const float*)d_in[5];
    const float* W2  = (const float*)d_in[6];
    const float* g2  = (const float*)d_in[7];
    const float* b2  = (const float*)d_in[8];
    const float* m2  = (const float*)d_in[9];
    const float* v2  = (const float*)d_in[10];
    float* out = (float*)d_out;

    knn_kernel<<<dim3(NP / 128, BT), 256>>>(x);
    uv_kernel<<<(BT * NP * 64) / 256, 256>>>(x, W1, g1, b1, m1, v1);
    mlp_kernel<<<(BT * NP) / 16, 128>>>(W2, g2, b2, m2, v2, out);
}